// round 3
// baseline (speedup 1.0000x reference)
#include <cuda_runtime.h>
#include <stdint.h>

#define MAX_NODES 100000
#define MAX_EDGES 1600000
#define D 128

// ---- device scratch (statics are the sanctioned scratch mechanism) ----
__device__ __align__(256) int   g_deg[MAX_NODES];
__device__ __align__(256) int   g_off[MAX_NODES + 1];
__device__ __align__(256) int   g_cur[MAX_NODES];
__device__ __align__(256) int   g_srcs[MAX_EDGES];
__device__ __align__(256) float g_wts[MAX_EDGES];
__device__ __align__(256) float g_agg[(size_t)MAX_NODES * D];

// ---------------------------------------------------------------------------
__global__ void zero_deg_kernel(int n) {
    int i = blockIdx.x * blockDim.x + threadIdx.x;
    if (i < n) g_deg[i] = 0;
}

// edge_index is int32 on device (harness dtype set is f32/i32/bf16; JAX x64-off
// downcasts the reference's int64). Guard indices so a wrong-dtype read fails
// numerically instead of trapping.
__global__ void count_kernel(const int* __restrict__ ei, int E, int N) {
    int e = blockIdx.x * blockDim.x + threadIdx.x;
    if (e < E) {
        int dst = ei[E + e];
        if ((unsigned)dst < (unsigned)N) atomicAdd(&g_deg[dst], 1);
    }
}

// Single-block exclusive scan, 8 elements/thread per chunk.
__global__ void scan_kernel(int n) {
    __shared__ int warp_sums[32];
    __shared__ int s_carry;
    const int tid  = threadIdx.x;
    const int lane = tid & 31;
    const int wid  = tid >> 5;
    if (tid == 0) s_carry = 0;
    __syncthreads();
    const int CHUNK = 1024 * 8;
    for (int base = 0; base < n; base += CHUNK) {
        int i0 = base + tid * 8;
        int v[8];
        #pragma unroll
        for (int j = 0; j < 8; j++) v[j] = (i0 + j < n) ? g_deg[i0 + j] : 0;
        int p[8];
        p[0] = v[0];
        #pragma unroll
        for (int j = 1; j < 8; j++) p[j] = p[j - 1] + v[j];
        int tsum = p[7];
        int incl = tsum;
        #pragma unroll
        for (int d = 1; d < 32; d <<= 1) {
            int t = __shfl_up_sync(0xFFFFFFFFu, incl, d);
            if (lane >= d) incl += t;
        }
        if (lane == 31) warp_sums[wid] = incl;
        __syncthreads();
        if (wid == 0) {
            int wv = warp_sums[lane];
            #pragma unroll
            for (int d = 1; d < 32; d <<= 1) {
                int t = __shfl_up_sync(0xFFFFFFFFu, wv, d);
                if (lane >= d) wv += t;
            }
            warp_sums[lane] = wv;
        }
        __syncthreads();
        int warp_base = (wid > 0) ? warp_sums[wid - 1] : 0;
        int texcl = s_carry + warp_base + (incl - tsum);
        #pragma unroll
        for (int j = 0; j < 8; j++) {
            int idx = i0 + j;
            if (idx < n) {
                int ex = texcl + p[j] - v[j];
                g_off[idx] = ex;
                g_cur[idx] = ex;
            }
        }
        __syncthreads();
        if (tid == 0) s_carry += warp_sums[31];
        __syncthreads();
    }
    if (tid == 0) g_off[n] = s_carry;
}

__global__ void fill_kernel(const int* __restrict__ ei,
                            const float* __restrict__ ew, int E, int N) {
    int e = blockIdx.x * blockDim.x + threadIdx.x;
    if (e < E) {
        int src = ei[e];
        int dst = ei[E + e];
        if ((unsigned)dst < (unsigned)N && (unsigned)src < (unsigned)N) {
            int pos = atomicAdd(&g_cur[dst], 1);
            g_srcs[pos] = src;
            g_wts[pos]  = ew[e];
        }
    }
}

// One warp per node: register accumulation, 2-deep gather for MLP.
__global__ void aggregate_kernel(const float* __restrict__ x, int n) {
    int gw   = (blockIdx.x * blockDim.x + threadIdx.x) >> 5;
    int lane = threadIdx.x & 31;
    if (gw >= n) return;
    int i   = g_off[gw];
    int end = g_off[gw + 1];
    float4 acc  = make_float4(0.f, 0.f, 0.f, 0.f);
    float4 acc2 = make_float4(0.f, 0.f, 0.f, 0.f);
    for (; i + 2 <= end; i += 2) {
        int   sa = g_srcs[i];
        int   sb = g_srcs[i + 1];
        float wa = g_wts[i];
        float wb = g_wts[i + 1];
        float4 va = *((const float4*)(x + (size_t)sa * D) + lane);
        float4 vb = *((const float4*)(x + (size_t)sb * D) + lane);
        acc.x  += wa * va.x; acc.y  += wa * va.y; acc.z  += wa * va.z; acc.w  += wa * va.w;
        acc2.x += wb * vb.x; acc2.y += wb * vb.y; acc2.z += wb * vb.z; acc2.w += wb * vb.w;
    }
    if (i < end) {
        int   sa = g_srcs[i];
        float wa = g_wts[i];
        float4 va = *((const float4*)(x + (size_t)sa * D) + lane);
        acc.x += wa * va.x; acc.y += wa * va.y; acc.z += wa * va.z; acc.w += wa * va.w;
    }
    float4 r = make_float4(acc.x + acc2.x, acc.y + acc2.y,
                           acc.z + acc2.z, acc.w + acc2.w);
    *((float4*)(g_agg + (size_t)gw * D) + lane) = r;
}

// out[m][n] = sum_k agg[m][k] * W[n][k] + b[n].
// 256 thr, tile 64(M) x 128(N), per-thread 4x8, K-chunks of 32.
__global__ __launch_bounds__(256) void gemm_kernel(const float* __restrict__ W,
                                                   const float* __restrict__ b,
                                                   float* __restrict__ out, int M) {
    __shared__ __align__(16) float ws[32][128];   // ws[k][n] = W[n][kb+k]
    __shared__ __align__(16) float xs[64][33];    // xs[m][k] (padded)
    const int tid = threadIdx.x;
    const int tn  = tid & 15;       // n0 = tn*8
    const int tm  = tid >> 4;       // m0 = tm*4
    const int mb  = blockIdx.x * 64;

    float acc[4][8];
    #pragma unroll
    for (int i = 0; i < 4; i++)
        #pragma unroll
        for (int j = 0; j < 8; j++) acc[i][j] = 0.f;

    for (int kb = 0; kb < 128; kb += 32) {
        for (int idx = tid; idx < 32 * 128; idx += 256) {
            int nn = idx & 127, kk = idx >> 7;
            ws[kk][nn] = W[nn * 128 + kb + kk];
        }
        for (int idx = tid; idx < 64 * 32; idx += 256) {
            int kk = idx & 31, mm = idx >> 5;
            int row = mb + mm;
            xs[mm][kk] = (row < M) ? g_agg[(size_t)row * 128 + kb + kk] : 0.f;
        }
        __syncthreads();
        #pragma unroll
        for (int k = 0; k < 32; k++) {
            float a0 = xs[tm * 4 + 0][k];
            float a1 = xs[tm * 4 + 1][k];
            float a2 = xs[tm * 4 + 2][k];
            float a3 = xs[tm * 4 + 3][k];
            float4 w0 = *(const float4*)&ws[k][tn * 8];
            float4 w1 = *(const float4*)&ws[k][tn * 8 + 4];
            acc[0][0] += a0 * w0.x; acc[0][1] += a0 * w0.y; acc[0][2] += a0 * w0.z; acc[0][3] += a0 * w0.w;
            acc[0][4] += a0 * w1.x; acc[0][5] += a0 * w1.y; acc[0][6] += a0 * w1.z; acc[0][7] += a0 * w1.w;
            acc[1][0] += a1 * w0.x; acc[1][1] += a1 * w0.y; acc[1][2] += a1 * w0.z; acc[1][3] += a1 * w0.w;
            acc[1][4] += a1 * w1.x; acc[1][5] += a1 * w1.y; acc[1][6] += a1 * w1.z; acc[1][7] += a1 * w1.w;
            acc[2][0] += a2 * w0.x; acc[2][1] += a2 * w0.y; acc[2][2] += a2 * w0.z; acc[2][3] += a2 * w0.w;
            acc[2][4] += a2 * w1.x; acc[2][5] += a2 * w1.y; acc[2][6] += a2 * w1.z; acc[2][7] += a2 * w1.w;
            acc[3][0] += a3 * w0.x; acc[3][1] += a3 * w0.y; acc[3][2] += a3 * w0.z; acc[3][3] += a3 * w0.w;
            acc[3][4] += a3 * w1.x; acc[3][5] += a3 * w1.y; acc[3][6] += a3 * w1.z; acc[3][7] += a3 * w1.w;
        }
        __syncthreads();
    }

    float bias[8];
    #pragma unroll
    for (int j = 0; j < 8; j++) bias[j] = b[tn * 8 + j];
    #pragma unroll
    for (int i = 0; i < 4; i++) {
        int row = mb + tm * 4 + i;
        if (row < M) {
            float4 o0 = make_float4(acc[i][0] + bias[0], acc[i][1] + bias[1],
                                    acc[i][2] + bias[2], acc[i][3] + bias[3]);
            float4 o1 = make_float4(acc[i][4] + bias[4], acc[i][5] + bias[5],
                                    acc[i][6] + bias[6], acc[i][7] + bias[7]);
            *(float4*)(out + (size_t)row * 128 + tn * 8)     = o0;
            *(float4*)(out + (size_t)row * 128 + tn * 8 + 4) = o1;
        }
    }
}

// ---------------------------------------------------------------------------
extern "C" void kernel_launch(void* const* d_in, const int* in_sizes, int n_in,
                              void* d_out, int out_size) {
    const float* x  = (const float*)d_in[0];
    const int*   ei = (const int*)d_in[1];     // int32 edge_index [2, E]
    const float* ew = (const float*)d_in[2];
    const float* W  = (const float*)d_in[3];
    const float* b  = (const float*)d_in[4];
    float*       out = (float*)d_out;

    int N = in_sizes[0] / D;      // 100000
    int E = in_sizes[2];          // 1600000

    zero_deg_kernel<<<(N + 255) / 256, 256>>>(N);
    count_kernel<<<(E + 255) / 256, 256>>>(ei, E, N);
    scan_kernel<<<1, 1024>>>(N);
    fill_kernel<<<(E + 255) / 256, 256>>>(ei, ew, E, N);
    aggregate_kernel<<<((size_t)N * 32 + 255) / 256, 256>>>(x, N);
    gemm_kernel<<<(N + 63) / 64, 256>>>(W, b, out, N);
}

// round 4
// speedup vs baseline: 1.9755x; 1.9755x over previous
#include <cuda_runtime.h>
#include <stdint.h>

#define MAX_NODES 100000
#define MAX_EDGES 1600000
#define D 128

// ---- device scratch ----
__device__ __align__(256) int   g_deg[MAX_NODES];
__device__ __align__(256) int   g_off[MAX_NODES + 1];
__device__ __align__(256) int   g_cur[MAX_NODES];
__device__ __align__(256) int   g_bsum[128];
__device__ __align__(256) int   g_bsumx[128];
__device__ __align__(256) int   g_srcs[MAX_EDGES];
__device__ __align__(256) float g_wts[MAX_EDGES];
__device__ __align__(256) float g_agg[(size_t)MAX_NODES * D];

// ---------------------------------------------------------------------------
__global__ void zero_deg_kernel(int n) {
    int i = blockIdx.x * blockDim.x + threadIdx.x;
    if (i < n) g_deg[i] = 0;
}

__global__ void count_kernel(const int* __restrict__ ei, int E, int N) {
    int e = blockIdx.x * blockDim.x + threadIdx.x;
    if (e < E) {
        int dst = ei[E + e];
        if ((unsigned)dst < (unsigned)N) atomicAdd(&g_deg[dst], 1);
    }
}

// ---- hierarchical scan: stage 1 — per-block (1024-wide) exclusive scan ----
__global__ __launch_bounds__(1024) void scan_blocks_kernel(int n) {
    __shared__ int warp_sums[32];
    const int tid  = threadIdx.x;
    const int lane = tid & 31;
    const int wid  = tid >> 5;
    const int i    = blockIdx.x * 1024 + tid;

    int v = (i < n) ? g_deg[i] : 0;
    int incl = v;
    #pragma unroll
    for (int d = 1; d < 32; d <<= 1) {
        int t = __shfl_up_sync(0xFFFFFFFFu, incl, d);
        if (lane >= d) incl += t;
    }
    if (lane == 31) warp_sums[wid] = incl;
    __syncthreads();
    if (wid == 0) {
        int wv = warp_sums[lane];
        #pragma unroll
        for (int d = 1; d < 32; d <<= 1) {
            int t = __shfl_up_sync(0xFFFFFFFFu, wv, d);
            if (lane >= d) wv += t;
        }
        warp_sums[lane] = wv;
    }
    __syncthreads();
    int base = (wid > 0) ? warp_sums[wid - 1] : 0;
    if (i < n) g_off[i] = base + incl - v;           // exclusive within block
    if (tid == 1023) g_bsum[blockIdx.x] = warp_sums[31];
}

// ---- stage 2 — scan the (<=128) block sums, write grand total ----
__global__ void scan_bsum_kernel(int nb, int n) {
    __shared__ int wsum[4];
    const int t    = threadIdx.x;       // 128 threads
    const int lane = t & 31;
    const int wid  = t >> 5;
    int v = (t < nb) ? g_bsum[t] : 0;
    int incl = v;
    #pragma unroll
    for (int d = 1; d < 32; d <<= 1) {
        int s = __shfl_up_sync(0xFFFFFFFFu, incl, d);
        if (lane >= d) incl += s;
    }
    if (lane == 31) wsum[wid] = incl;
    __syncthreads();
    int base = 0;
    #pragma unroll
    for (int j = 0; j < 4; j++) base += (j < wid) ? wsum[j] : 0;
    if (t < nb) g_bsumx[t] = base + incl - v;
    if (t == 0) g_off[n] = wsum[0] + wsum[1] + wsum[2] + wsum[3];
}

// ---- stage 3 — add block bases, mirror into cursors ----
__global__ __launch_bounds__(1024) void scan_add_kernel(int n) {
    int i = blockIdx.x * 1024 + threadIdx.x;
    if (i < n) {
        int val = g_off[i] + g_bsumx[blockIdx.x];
        g_off[i] = val;
        g_cur[i] = val;
    }
}

__global__ void fill_kernel(const int* __restrict__ ei,
                            const float* __restrict__ ew, int E, int N) {
    int e = blockIdx.x * blockDim.x + threadIdx.x;
    if (e < E) {
        int src = ei[e];
        int dst = ei[E + e];
        if ((unsigned)dst < (unsigned)N && (unsigned)src < (unsigned)N) {
            int pos = atomicAdd(&g_cur[dst], 1);
            g_srcs[pos] = src;
            g_wts[pos]  = ew[e];
        }
    }
}

// One warp per node; 4-deep unrolled gather for MLP.
__global__ void aggregate_kernel(const float* __restrict__ x, int n) {
    int gw   = (blockIdx.x * blockDim.x + threadIdx.x) >> 5;
    int lane = threadIdx.x & 31;
    if (gw >= n) return;
    int i   = g_off[gw];
    int end = g_off[gw + 1];
    float4 a0 = make_float4(0.f, 0.f, 0.f, 0.f);
    float4 a1 = make_float4(0.f, 0.f, 0.f, 0.f);
    float4 a2 = make_float4(0.f, 0.f, 0.f, 0.f);
    float4 a3 = make_float4(0.f, 0.f, 0.f, 0.f);
    for (; i + 4 <= end; i += 4) {
        int   s0 = g_srcs[i],     s1 = g_srcs[i + 1];
        int   s2 = g_srcs[i + 2], s3 = g_srcs[i + 3];
        float w0 = g_wts[i],      w1 = g_wts[i + 1];
        float w2 = g_wts[i + 2],  w3 = g_wts[i + 3];
        float4 v0 = *((const float4*)(x + (size_t)s0 * D) + lane);
        float4 v1 = *((const float4*)(x + (size_t)s1 * D) + lane);
        float4 v2 = *((const float4*)(x + (size_t)s2 * D) + lane);
        float4 v3 = *((const float4*)(x + (size_t)s3 * D) + lane);
        a0.x += w0 * v0.x; a0.y += w0 * v0.y; a0.z += w0 * v0.z; a0.w += w0 * v0.w;
        a1.x += w1 * v1.x; a1.y += w1 * v1.y; a1.z += w1 * v1.z; a1.w += w1 * v1.w;
        a2.x += w2 * v2.x; a2.y += w2 * v2.y; a2.z += w2 * v2.z; a2.w += w2 * v2.w;
        a3.x += w3 * v3.x; a3.y += w3 * v3.y; a3.z += w3 * v3.z; a3.w += w3 * v3.w;
    }
    for (; i < end; i++) {
        int   s = g_srcs[i];
        float w = g_wts[i];
        float4 v = *((const float4*)(x + (size_t)s * D) + lane);
        a0.x += w * v.x; a0.y += w * v.y; a0.z += w * v.z; a0.w += w * v.w;
    }
    float4 r = make_float4(a0.x + a1.x + a2.x + a3.x,
                           a0.y + a1.y + a2.y + a3.y,
                           a0.z + a1.z + a2.z + a3.z,
                           a0.w + a1.w + a2.w + a3.w);
    *((float4*)(g_agg + (size_t)gw * D) + lane) = r;
}

// out[m][n] = sum_k agg[m][k]*W[n][k] + b[n].
// 256 thr, tile 128(M) x 128(N), per-thread 8x8, K-chunks of 32.
// Both smem tiles stored k-major [32][132]: coalesced global loads,
// 16B-aligned vector LDS (132*4B = 528B row stride, multiple of 16).
__global__ __launch_bounds__(256) void gemm_kernel(const float* __restrict__ W,
                                                   const float* __restrict__ b,
                                                   float* __restrict__ out, int M) {
    __shared__ __align__(16) float ws[32][132];   // ws[k][n] = W[n][kb+k]
    __shared__ __align__(16) float xs[32][132];   // xs[k][m] = agg[mb+m][kb+k]
    const int tid = threadIdx.x;
    const int tn  = tid & 15;        // n0 = tn*8
    const int tm  = tid >> 4;        // m0 = tm*8
    const int mb  = blockIdx.x * 128;

    float acc[8][8];
    #pragma unroll
    for (int i = 0; i < 8; i++)
        #pragma unroll
        for (int j = 0; j < 8; j++) acc[i][j] = 0.f;

    for (int kb = 0; kb < 128; kb += 32) {
        // W tile: 128 rows x 32 k. consecutive tid -> consecutive k (coalesced).
        #pragma unroll
        for (int idx = tid; idx < 128 * 32; idx += 256) {
            int kk = idx & 31, nn = idx >> 5;
            ws[kk][nn] = W[nn * 128 + kb + kk];
        }
        // agg tile: 128 rows x 32 k, same mapping.
        #pragma unroll
        for (int idx = tid; idx < 128 * 32; idx += 256) {
            int kk = idx & 31, mm = idx >> 5;
            int row = mb + mm;
            xs[kk][mm] = (row < M) ? g_agg[(size_t)row * 128 + kb + kk] : 0.f;
        }
        __syncthreads();
        #pragma unroll
        for (int k = 0; k < 32; k++) {
            float4 x0 = *(const float4*)&xs[k][tm * 8];
            float4 x1 = *(const float4*)&xs[k][tm * 8 + 4];
            float4 w0 = *(const float4*)&ws[k][tn * 8];
            float4 w1 = *(const float4*)&ws[k][tn * 8 + 4];
            float av[8] = {x0.x, x0.y, x0.z, x0.w, x1.x, x1.y, x1.z, x1.w};
            float wv[8] = {w0.x, w0.y, w0.z, w0.w, w1.x, w1.y, w1.z, w1.w};
            #pragma unroll
            for (int i = 0; i < 8; i++)
                #pragma unroll
                for (int j = 0; j < 8; j++)
                    acc[i][j] += av[i] * wv[j];
        }
        __syncthreads();
    }

    float bias[8];
    #pragma unroll
    for (int j = 0; j < 8; j++) bias[j] = b[tn * 8 + j];
    #pragma unroll
    for (int i = 0; i < 8; i++) {
        int row = mb + tm * 8 + i;
        if (row < M) {
            float4 o0 = make_float4(acc[i][0] + bias[0], acc[i][1] + bias[1],
                                    acc[i][2] + bias[2], acc[i][3] + bias[3]);
            float4 o1 = make_float4(acc[i][4] + bias[4], acc[i][5] + bias[5],
                                    acc[i][6] + bias[6], acc[i][7] + bias[7]);
            *(float4*)(out + (size_t)row * 128 + tn * 8)     = o0;
            *(float4*)(out + (size_t)row * 128 + tn * 8 + 4) = o1;
        }
    }
}

// ---------------------------------------------------------------------------
extern "C" void kernel_launch(void* const* d_in, const int* in_sizes, int n_in,
                              void* d_out, int out_size) {
    const float* x  = (const float*)d_in[0];
    const int*   ei = (const int*)d_in[1];     // int32 edge_index [2, E]
    const float* ew = (const float*)d_in[2];
    const float* W  = (const float*)d_in[3];
    const float* b  = (const float*)d_in[4];
    float*       out = (float*)d_out;

    int N = in_sizes[0] / D;      // 100000
    int E = in_sizes[2];          // 1600000
    int nb = (N + 1023) / 1024;   // 98

    zero_deg_kernel<<<(N + 255) / 256, 256>>>(N);
    count_kernel<<<(E + 255) / 256, 256>>>(ei, E, N);
    scan_blocks_kernel<<<nb, 1024>>>(N);
    scan_bsum_kernel<<<1, 128>>>(nb, N);
    scan_add_kernel<<<nb, 1024>>>(N);
    fill_kernel<<<(E + 255) / 256, 256>>>(ei, ew, E, N);
    aggregate_kernel<<<((size_t)N * 32 + 255) / 256, 256>>>(x, N);
    gemm_kernel<<<(N + 127) / 128, 256>>>(W, b, out, N);
}

// round 6
// speedup vs baseline: 2.0987x; 1.0624x over previous
#include <cuda_runtime.h>
#include <stdint.h>

#define MAX_NODES 100000
#define MAX_EDGES 1600000
#define D 128

// ---- device scratch ----
__device__ __align__(256) int   g_deg[MAX_NODES];
__device__ __align__(256) int   g_off[MAX_NODES + 1];
__device__ __align__(256) int   g_cur[MAX_NODES];
__device__ __align__(256) int   g_bsum[128];
__device__ __align__(256) int   g_bsumx[128];
__device__ __align__(256) int   g_srcs[MAX_EDGES];
__device__ __align__(256) float g_wts[MAX_EDGES];
__device__ __align__(256) float g_agg[(size_t)MAX_NODES * D];

// ---------------------------------------------------------------------------
__global__ void zero_deg_kernel(int n) {
    int i = blockIdx.x * blockDim.x + threadIdx.x;
    if (i < n) g_deg[i] = 0;
}

__global__ void count_kernel(const int* __restrict__ ei, int E, int N) {
    int e = blockIdx.x * blockDim.x + threadIdx.x;
    if (e < E) {
        int dst = ei[E + e];
        if ((unsigned)dst < (unsigned)N) atomicAdd(&g_deg[dst], 1);
    }
}

__global__ __launch_bounds__(1024) void scan_blocks_kernel(int n) {
    __shared__ int warp_sums[32];
    const int tid  = threadIdx.x;
    const int lane = tid & 31;
    const int wid  = tid >> 5;
    const int i    = blockIdx.x * 1024 + tid;

    int v = (i < n) ? g_deg[i] : 0;
    int incl = v;
    #pragma unroll
    for (int d = 1; d < 32; d <<= 1) {
        int t = __shfl_up_sync(0xFFFFFFFFu, incl, d);
        if (lane >= d) incl += t;
    }
    if (lane == 31) warp_sums[wid] = incl;
    __syncthreads();
    if (wid == 0) {
        int wv = warp_sums[lane];
        #pragma unroll
        for (int d = 1; d < 32; d <<= 1) {
            int t = __shfl_up_sync(0xFFFFFFFFu, wv, d);
            if (lane >= d) wv += t;
        }
        warp_sums[lane] = wv;
    }
    __syncthreads();
    int base = (wid > 0) ? warp_sums[wid - 1] : 0;
    if (i < n) g_off[i] = base + incl - v;
    if (tid == 1023) g_bsum[blockIdx.x] = warp_sums[31];
}

__global__ void scan_bsum_kernel(int nb, int n) {
    __shared__ int wsum[4];
    const int t    = threadIdx.x;
    const int lane = t & 31;
    const int wid  = t >> 5;
    int v = (t < nb) ? g_bsum[t] : 0;
    int incl = v;
    #pragma unroll
    for (int d = 1; d < 32; d <<= 1) {
        int s = __shfl_up_sync(0xFFFFFFFFu, incl, d);
        if (lane >= d) incl += s;
    }
    if (lane == 31) wsum[wid] = incl;
    __syncthreads();
    int base = 0;
    #pragma unroll
    for (int j = 0; j < 4; j++) base += (j < wid) ? wsum[j] : 0;
    if (t < nb) g_bsumx[t] = base + incl - v;
    if (t == 0) g_off[n] = wsum[0] + wsum[1] + wsum[2] + wsum[3];
}

__global__ __launch_bounds__(1024) void scan_add_kernel(int n) {
    int i = blockIdx.x * 1024 + threadIdx.x;
    if (i < n) {
        int val = g_off[i] + g_bsumx[blockIdx.x];
        g_off[i] = val;
        g_cur[i] = val;
    }
}

__global__ void fill_kernel(const int* __restrict__ ei,
                            const float* __restrict__ ew, int E, int N) {
    int e = blockIdx.x * blockDim.x + threadIdx.x;
    if (e < E) {
        int src = ei[e];
        int dst = ei[E + e];
        if ((unsigned)dst < (unsigned)N && (unsigned)src < (unsigned)N) {
            int pos = atomicAdd(&g_cur[dst], 1);
            g_srcs[pos] = src;
            g_wts[pos]  = ew[e];
        }
    }
}

// One warp per node; 4-deep unrolled gather for MLP.
__global__ void aggregate_kernel(const float* __restrict__ x, int n) {
    int gw   = (blockIdx.x * blockDim.x + threadIdx.x) >> 5;
    int lane = threadIdx.x & 31;
    if (gw >= n) return;
    int i   = g_off[gw];
    int end = g_off[gw + 1];
    float4 a0 = make_float4(0.f, 0.f, 0.f, 0.f);
    float4 a1 = make_float4(0.f, 0.f, 0.f, 0.f);
    float4 a2 = make_float4(0.f, 0.f, 0.f, 0.f);
    float4 a3 = make_float4(0.f, 0.f, 0.f, 0.f);
    for (; i + 4 <= end; i += 4) {
        int   s0 = g_srcs[i],     s1 = g_srcs[i + 1];
        int   s2 = g_srcs[i + 2], s3 = g_srcs[i + 3];
        float w0 = g_wts[i],      w1 = g_wts[i + 1];
        float w2 = g_wts[i + 2],  w3 = g_wts[i + 3];
        float4 v0 = *((const float4*)(x + (size_t)s0 * D) + lane);
        float4 v1 = *((const float4*)(x + (size_t)s1 * D) + lane);
        float4 v2 = *((const float4*)(x + (size_t)s2 * D) + lane);
        float4 v3 = *((const float4*)(x + (size_t)s3 * D) + lane);
        a0.x += w0 * v0.x; a0.y += w0 * v0.y; a0.z += w0 * v0.z; a0.w += w0 * v0.w;
        a1.x += w1 * v1.x; a1.y += w1 * v1.y; a1.z += w1 * v1.z; a1.w += w1 * v1.w;
        a2.x += w2 * v2.x; a2.y += w2 * v2.y; a2.z += w2 * v2.z; a2.w += w2 * v2.w;
        a3.x += w3 * v3.x; a3.y += w3 * v3.y; a3.z += w3 * v3.z; a3.w += w3 * v3.w;
    }
    for (; i < end; i++) {
        int   s = g_srcs[i];
        float w = g_wts[i];
        float4 v = *((const float4*)(x + (size_t)s * D) + lane);
        a0.x += w * v.x; a0.y += w * v.y; a0.z += w * v.z; a0.w += w * v.w;
    }
    float4 r = make_float4(a0.x + a1.x + a2.x + a3.x,
                           a0.y + a1.y + a2.y + a3.y,
                           a0.z + a1.z + a2.z + a3.z,
                           a0.w + a1.w + a2.w + a3.w);
    *((float4*)(g_agg + (size_t)gw * D) + lane) = r;
}

// ============================================================================
// SIMT GEMM with packed f32x2 FMAs (Blackwell base-family dual-fp32 pipe).
// out[m][n] = sum_k agg[m][k]*W[n][k] + b[n].
// 256 thr, tile 128(M) x 128(N), per-thread 8x8 (as 8 x 4 f32x2 pairs),
// K-chunks of 32. Tiles k-major [32][132] (coalesced loads, 16B-aligned LDS).
// ============================================================================

__device__ __forceinline__ unsigned long long pack_dup(float a) {
    unsigned long long r;
    unsigned int u = __float_as_uint(a);
    asm("mov.b64 %0, {%1, %2};" : "=l"(r) : "r"(u), "r"(u));
    return r;
}

__device__ __forceinline__ void fma_x2(unsigned long long& acc,
                                       unsigned long long a,
                                       unsigned long long w) {
    asm("fma.rn.f32x2 %0, %1, %2, %0;" : "+l"(acc) : "l"(a), "l"(w));
}

__global__ __launch_bounds__(256) void gemm_kernel(const float* __restrict__ W,
                                                   const float* __restrict__ b,
                                                   float* __restrict__ out, int M) {
    __shared__ __align__(16) float ws[32][132];   // ws[k][n] = W[n][kb+k]
    __shared__ __align__(16) float xs[32][132];   // xs[k][m] = agg[mb+m][kb+k]
    const int tid = threadIdx.x;
    const int tn  = tid & 15;        // n0 = tn*8
    const int tm  = tid >> 4;        // m0 = tm*8
    const int mb  = blockIdx.x * 128;

    unsigned long long acc[8][4];    // [m][n-pair], each = 2 packed fp32
    #pragma unroll
    for (int i = 0; i < 8; i++)
        #pragma unroll
        for (int j = 0; j < 4; j++) acc[i][j] = 0ULL;

    for (int kb = 0; kb < 128; kb += 32) {
        #pragma unroll
        for (int idx = tid; idx < 128 * 32; idx += 256) {
            int kk = idx & 31, nn = idx >> 5;
            ws[kk][nn] = W[nn * 128 + kb + kk];
        }
        #pragma unroll
        for (int idx = tid; idx < 128 * 32; idx += 256) {
            int kk = idx & 31, mm = idx >> 5;
            int row = mb + mm;
            xs[kk][mm] = (row < M) ? g_agg[(size_t)row * 128 + kb + kk] : 0.f;
        }
        __syncthreads();
        #pragma unroll
        for (int k = 0; k < 32; k++) {
            float4 x0 = *(const float4*)&xs[k][tm * 8];
            float4 x1 = *(const float4*)&xs[k][tm * 8 + 4];
            // w pairs: (n0,n1)(n2,n3)(n4,n5)(n6,n7) — low word = even n.
            const unsigned long long* wp =
                (const unsigned long long*)&ws[k][tn * 8];
            unsigned long long w0 = wp[0], w1 = wp[1], w2 = wp[2], w3 = wp[3];
            float av[8] = {x0.x, x0.y, x0.z, x0.w, x1.x, x1.y, x1.z, x1.w};
            #pragma unroll
            for (int i = 0; i < 8; i++) {
                unsigned long long ad = pack_dup(av[i]);
                fma_x2(acc[i][0], ad, w0);
                fma_x2(acc[i][1], ad, w1);
                fma_x2(acc[i][2], ad, w2);
                fma_x2(acc[i][3], ad, w3);
            }
        }
        __syncthreads();
    }

    float bias[8];
    #pragma unroll
    for (int j = 0; j < 8; j++) bias[j] = b[tn * 8 + j];
    #pragma unroll
    for (int i = 0; i < 8; i++) {
        int row = mb + tm * 8 + i;
        if (row < M) {
            float r[8];
            #pragma unroll
            for (int j = 0; j < 4; j++) {
                unsigned int lo, hi;
                asm("mov.b64 {%0, %1}, %2;" : "=r"(lo), "=r"(hi) : "l"(acc[i][j]));
                r[j * 2]     = __uint_as_float(lo);
                r[j * 2 + 1] = __uint_as_float(hi);
            }
            float4 o0 = make_float4(r[0] + bias[0], r[1] + bias[1],
                                    r[2] + bias[2], r[3] + bias[3]);
            float4 o1 = make_float4(r[4] + bias[4], r[5] + bias[5],
                                    r[6] + bias[6], r[7] + bias[7]);
            *(float4*)(out + (size_t)row * 128 + tn * 8)     = o0;
            *(float4*)(out + (size_t)row * 128 + tn * 8 + 4) = o1;
        }
    }
}

// ---------------------------------------------------------------------------
extern "C" void kernel_launch(void* const* d_in, const int* in_sizes, int n_in,
                              void* d_out, int out_size) {
    const float* x  = (const float*)d_in[0];
    const int*   ei = (const int*)d_in[1];     // int32 edge_index [2, E]
    const float* ew = (const float*)d_in[2];
    const float* W  = (const float*)d_in[3];
    const float* b  = (const float*)d_in[4];
    float*       out = (float*)d_out;

    int N = in_sizes[0] / D;      // 100000
    int E = in_sizes[2];          // 1600000
    int nb = (N + 1023) / 1024;   // 98

    zero_deg_kernel<<<(N + 255) / 256, 256>>>(N);
    count_kernel<<<(E + 255) / 256, 256>>>(ei, E, N);
    scan_blocks_kernel<<<nb, 1024>>>(N);
    scan_bsum_kernel<<<1, 128>>>(nb, N);
    scan_add_kernel<<<nb, 1024>>>(N);
    fill_kernel<<<(E + 255) / 256, 256>>>(ei, ew, E, N);
    aggregate_kernel<<<((size_t)N * 32 + 255) / 256, 256>>>(x, N);
    gemm_kernel<<<(N + 127) / 128, 256>>>(W, b, out, N);
}